// round 12
// baseline (speedup 1.0000x reference)
#include <cuda_runtime.h>

typedef unsigned long long u64;

#define NRAYS 32768
#define THREADS 128
#define RAYS_PER_BLOCK (THREADS * 2)            // 2 rays per thread
#define NBLK (NRAYS / RAYS_PER_BLOCK)           // 128 march blocks + 128 scan blocks

// ---- packed f32x2 helpers (Blackwell sm_103a) ----
__device__ __forceinline__ u64 pack2(float a, float b) {
    u64 r; asm("mov.b64 %0, {%1, %2};" : "=l"(r) : "f"(a), "f"(b)); return r;
}
__device__ __forceinline__ float2 unpack2(u64 v) {
    float2 r; asm("mov.b64 {%0, %1}, %2;" : "=f"(r.x), "=f"(r.y) : "l"(v)); return r;
}
__device__ __forceinline__ u64 ffma2(u64 a, u64 b, u64 c) {
    u64 d; asm("fma.rn.f32x2 %0, %1, %2, %3;" : "=l"(d) : "l"(a), "l"(b), "l"(c)); return d;
}
__device__ __forceinline__ u64 fadd2(u64 a, u64 b) {
    u64 d; asm("add.rn.f32x2 %0, %1, %2;" : "=l"(d) : "l"(a), "l"(b)); return d;
}
__device__ __forceinline__ u64 relu2(u64 v) {
    float2 f = unpack2(v);
    return pack2(fmaxf(f.x, 0.0f), fmaxf(f.y, 0.0f));
}
__device__ __forceinline__ u64 splat2(float x) { return pack2(x, x); }

struct __align__(16) Weights {
    float W0[3 * 64];
    float b0[64];
    float W1[64 * 64];
    float b1[64];
    float W2[64];
    float b2;
    float pad[3];
    float Wr0[6 * 64];
    float br0[64];
    float Wr1[64 * 3];
    float br1[3];
};

// Two-point SDF eval: every shared-memory weight load feeds FOUR ffma2
// (2 neurons x 2 rays) — halves L1tex traffic per MAC (verified R9: L1
// 81->63.6%, fma 39->61.8%). Layer1 uses EIGHTH-tiles (8 neurons) in a
// DYNAMIC loop: shrinks acc live set to 16 regs so the kernel fits a
// 170-reg cap (3 CTAs/SM = 12 warps, up from 8). __noinline__ is
// load-bearing: it fences LICM of weight loads out of the march/scan
// loops (previously spilled ~10KB/thread).
__device__ __noinline__ float2 sdf_eval2(const Weights* __restrict__ sp,
                                         float pxA, float pyA, float pzA,
                                         float pxB, float pyB, float pzB) {
    const Weights& s = *sp;
    u64 hA[32], hB[32];
    {
        const float4* b4 = (const float4*)s.b0;
        #pragma unroll
        for (int q = 0; q < 16; q++) {
            float4 v = b4[q];
            u64 lo = pack2(v.x, v.y), hi = pack2(v.z, v.w);
            hA[2 * q] = lo; hA[2 * q + 1] = hi;
            hB[2 * q] = lo; hB[2 * q + 1] = hi;
        }
        float pa[3] = {pxA, pyA, pzA};
        float pb[3] = {pxB, pyB, pzB};
        #pragma unroll
        for (int i = 0; i < 3; i++) {
            u64 xA = splat2(pa[i]);
            u64 xB = splat2(pb[i]);
            const float4* w = (const float4*)(s.W0 + i * 64);
            #pragma unroll
            for (int q = 0; q < 16; q++) {
                float4 wv = w[q];
                u64 wlo = pack2(wv.x, wv.y), whi = pack2(wv.z, wv.w);
                hA[2 * q]     = ffma2(xA, wlo, hA[2 * q]);
                hA[2 * q + 1] = ffma2(xA, whi, hA[2 * q + 1]);
                hB[2 * q]     = ffma2(xB, wlo, hB[2 * q]);
                hB[2 * q + 1] = ffma2(xB, whi, hB[2 * q + 1]);
            }
        }
        #pragma unroll
        for (int q = 0; q < 32; q++) { hA[q] = relu2(hA[q]); hB[q] = relu2(hB[q]); }
    }

    u64 dA0 = 0ull, dA1 = 0ull, dB0 = 0ull, dB1 = 0ull;
    #pragma unroll 1
    for (int ot = 0; ot < 8; ot++) {
        u64 accA[4], accB[4];
        {
            const float4* b4 = (const float4*)(s.b1 + ot * 8);
            #pragma unroll
            for (int q = 0; q < 2; q++) {
                float4 v = b4[q];
                u64 lo = pack2(v.x, v.y), hi = pack2(v.z, v.w);
                accA[2 * q] = lo; accA[2 * q + 1] = hi;
                accB[2 * q] = lo; accB[2 * q + 1] = hi;
            }
        }
        const float4* wbase = (const float4*)(s.W1 + ot * 8);
        #pragma unroll
        for (int kk = 0; kk < 32; kk++) {
            float2 hpA = unpack2(hA[kk]);
            float2 hpB = unpack2(hB[kk]);
            {
                u64 xA = splat2(hpA.x), xB = splat2(hpB.x);
                const float4* w = wbase + (2 * kk) * 16;
                #pragma unroll
                for (int q = 0; q < 2; q++) {
                    float4 wv = w[q];
                    u64 wlo = pack2(wv.x, wv.y), whi = pack2(wv.z, wv.w);
                    accA[2 * q]     = ffma2(xA, wlo, accA[2 * q]);
                    accA[2 * q + 1] = ffma2(xA, whi, accA[2 * q + 1]);
                    accB[2 * q]     = ffma2(xB, wlo, accB[2 * q]);
                    accB[2 * q + 1] = ffma2(xB, whi, accB[2 * q + 1]);
                }
            }
            {
                u64 xA = splat2(hpA.y), xB = splat2(hpB.y);
                const float4* w = wbase + (2 * kk + 1) * 16;
                #pragma unroll
                for (int q = 0; q < 2; q++) {
                    float4 wv = w[q];
                    u64 wlo = pack2(wv.x, wv.y), whi = pack2(wv.z, wv.w);
                    accA[2 * q]     = ffma2(xA, wlo, accA[2 * q]);
                    accA[2 * q + 1] = ffma2(xA, whi, accA[2 * q + 1]);
                    accB[2 * q]     = ffma2(xB, wlo, accB[2 * q]);
                    accB[2 * q + 1] = ffma2(xB, whi, accB[2 * q + 1]);
                }
            }
        }
        // layer 2 (fused): relu then dot with W2 eighth
        const float4* w2 = (const float4*)(s.W2 + ot * 8);
        #pragma unroll
        for (int q = 0; q < 2; q++) {
            float4 wv = w2[q];
            u64 wlo = pack2(wv.x, wv.y), whi = pack2(wv.z, wv.w);
            dA0 = ffma2(relu2(accA[2 * q]),     wlo, dA0);
            dA1 = ffma2(relu2(accA[2 * q + 1]), whi, dA1);
            dB0 = ffma2(relu2(accB[2 * q]),     wlo, dB0);
            dB1 = ffma2(relu2(accB[2 * q + 1]), whi, dB1);
        }
    }
    float2 fa = unpack2(fadd2(dA0, dA1));
    float2 fb = unpack2(fadd2(dB0, dB1));
    return make_float2(fa.x + fa.y + s.b2, fb.x + fb.y + s.b2);
}

// Reflectance MLP: sigmoid(relu([p,d]@Wr0+br0)@Wr1+br1). Called once.
__device__ __noinline__ void refl_eval(const Weights* __restrict__ sp,
                                       const float* in6, float* rgb) {
    const Weights& s = *sp;
    u64 h[32];
    {
        const float4* b4 = (const float4*)s.br0;
        #pragma unroll
        for (int q = 0; q < 16; q++) {
            float4 v = b4[q];
            h[2 * q]     = pack2(v.x, v.y);
            h[2 * q + 1] = pack2(v.z, v.w);
        }
        #pragma unroll
        for (int i = 0; i < 6; i++) {
            u64 xi = splat2(in6[i]);
            const float4* w = (const float4*)(s.Wr0 + i * 64);
            #pragma unroll
            for (int q = 0; q < 16; q++) {
                float4 wv = w[q];
                h[2 * q]     = ffma2(xi, pack2(wv.x, wv.y), h[2 * q]);
                h[2 * q + 1] = ffma2(xi, pack2(wv.z, wv.w), h[2 * q + 1]);
            }
        }
    }
    float a0 = s.br1[0], a1 = s.br1[1], a2 = s.br1[2];
    #pragma unroll
    for (int kk = 0; kk < 32; kk++) {
        float2 hp = unpack2(h[kk]);
        float v0 = fmaxf(hp.x, 0.0f);
        float v1 = fmaxf(hp.y, 0.0f);
        const float* w = s.Wr1 + (2 * kk) * 3;
        a0 = fmaf(v0, w[0], a0);
        a1 = fmaf(v0, w[1], a1);
        a2 = fmaf(v0, w[2], a2);
        a0 = fmaf(v1, w[3], a0);
        a1 = fmaf(v1, w[4], a1);
        a2 = fmaf(v1, w[5], a2);
    }
    rgb[0] = 1.0f / (1.0f + expf(-a0));
    rgb[1] = 1.0f / (1.0f + expf(-a1));
    rgb[2] = 1.0f / (1.0f + expf(-a2));
}

// Grid = 2*NBLK 128-thread CTAs. Blocks [0,NBLK): march+reflectance,
// blocks [NBLK,2*NBLK): tput scan (2 rays/thread each). Tasks independent
// (scan uses identical weight values via stop_gradient); disjoint writes.
__global__ void __launch_bounds__(THREADS, 3) sdf_march_kernel(
    const float* __restrict__ rays,
    const float* __restrict__ gW0, const float* __restrict__ gb0,
    const float* __restrict__ gW1, const float* __restrict__ gb1,
    const float* __restrict__ gW2, const float* __restrict__ gb2,
    const float* __restrict__ gWr0, const float* __restrict__ gbr0,
    const float* __restrict__ gWr1, const float* __restrict__ gbr1,
    float* __restrict__ out)
{
    __shared__ Weights s;
    int tid = threadIdx.x;
    bool is_scan = blockIdx.x >= NBLK;
    int blk = blockIdx.x - (is_scan ? NBLK : 0);

    for (int i = tid; i < 3 * 64; i += THREADS) s.W0[i] = gW0[i];
    for (int i = tid; i < 64; i += THREADS) s.b0[i] = gb0[i];
    for (int i = tid; i < 64 * 64; i += THREADS) s.W1[i] = gW1[i];
    for (int i = tid; i < 64; i += THREADS) s.b1[i] = gb1[i];
    for (int i = tid; i < 64; i += THREADS) s.W2[i] = gW2[i];
    if (tid == 0) s.b2 = gb2[0];
    if (!is_scan) {  // only march blocks need the reflectance net
        for (int i = tid; i < 6 * 64; i += THREADS) s.Wr0[i] = gWr0[i];
        for (int i = tid; i < 64; i += THREADS) s.br0[i] = gbr0[i];
        for (int i = tid; i < 64 * 3; i += THREADS) s.Wr1[i] = gWr1[i];
        for (int i = tid; i < 3; i += THREADS) s.br1[i] = gbr1[i];
    }
    __syncthreads();

    int rayA = (blk * THREADS + tid) * 2;
    int rayB = rayA + 1;
    const float* ra = rays + rayA * 6;
    const float* rb = rays + rayB * 6;
    float roxA = ra[0], royA = ra[1], rozA = ra[2];
    float rdxA = ra[3], rdyA = ra[4], rdzA = ra[5];
    float roxB = rb[0], royB = rb[1], rozB = rb[2];
    float rdxB = rb[3], rdyB = rb[4], rdzB = rb[5];

    if (!is_scan) {
        // ---- sphere march (hit lanes freeze cd -> all-hit break is exact) ----
        float cdA = 0.0f, cdB = 0.0f;
        bool hitA = false, hitB = false;
        #pragma unroll 1
        for (int it = 0; it < 64; ++it) {
            asm volatile("" ::: "memory");   // block cross-iteration hoist/CSE
            float2 d = sdf_eval2(&s,
                fmaf(rdxA, cdA, roxA), fmaf(rdyA, cdA, royA), fmaf(rdzA, cdA, rozA),
                fmaf(rdxB, cdB, roxB), fmaf(rdyB, cdB, royB), fmaf(rdzB, cdB, rozB));
            bool hA = (d.x < 1e-4f) && (cdA >= 0.0f) && (cdA <= 1.0f);
            bool hB = (d.y < 1e-4f) && (cdB >= 0.0f) && (cdB <= 1.0f);
            hitA = hitA || hA;
            hitB = hitB || hB;
            if (!hitA) cdA += d.x;
            if (!hitB) cdB += d.y;
            if (__all_sync(0xffffffffu, hitA && hitB)) break;
        }

        // ---- reflectance (skipped entirely for all-miss warps) ----
        float rgbA[3] = {0.0f, 0.0f, 0.0f};
        float rgbB[3] = {0.0f, 0.0f, 0.0f};
        if (__any_sync(0xffffffffu, hitA || hitB)) {
            float in6A[6] = { fmaf(rdxA, cdA, roxA), fmaf(rdyA, cdA, royA),
                              fmaf(rdzA, cdA, rozA), rdxA, rdyA, rdzA };
            refl_eval(&s, in6A, rgbA);
            float in6B[6] = { fmaf(rdxB, cdB, roxB), fmaf(rdyB, cdB, royB),
                              fmaf(rdzB, cdB, rozB), rdxB, rdyB, rdzB };
            refl_eval(&s, in6B, rgbB);
            if (!hitA) { rgbA[0] = 0.0f; rgbA[1] = 0.0f; rgbA[2] = 0.0f; }
            if (!hitB) { rgbB[0] = 0.0f; rgbB[1] = 0.0f; rgbB[2] = 0.0f; }
        }
        out[4 * rayA + 0] = rgbA[0];
        out[4 * rayA + 1] = rgbA[1];
        out[4 * rayA + 2] = rgbA[2];
        out[4 * rayB + 0] = rgbB[0];
        out[4 * rayB + 1] = rgbB[1];
        out[4 * rayB + 2] = rgbB[2];
    } else {
        // ---- throughput argmin scan: t = step*i, i = 0..64 ----
        // tput = sdf(best_pos) equals the scan's running min (same weight
        // values, identical position arithmetic), so only the min is tracked.
        const float step = (1.0f + 1.0f / 64.0f) / 64.0f;  // 65/4096, exact fp32
        float2 cm = sdf_eval2(&s, roxA, royA, rozA, roxB, royB, rozB);
        #pragma unroll 1
        for (int i = 1; i <= 64; ++i) {
            asm volatile("" ::: "memory");   // block cross-iteration hoist/CSE
            float t = step * (float)i;
            float2 sd = sdf_eval2(&s,
                fmaf(rdxA, t, roxA), fmaf(rdyA, t, royA), fmaf(rdzA, t, rozA),
                fmaf(rdxB, t, roxB), fmaf(rdyB, t, royB), fmaf(rdzB, t, rozB));
            cm.x = fminf(cm.x, sd.x);
            cm.y = fminf(cm.y, sd.y);
        }
        out[4 * rayA + 3] = cm.x;
        out[4 * rayB + 3] = cm.y;
    }
}

extern "C" void kernel_launch(void* const* d_in, const int* in_sizes, int n_in,
                              void* d_out, int out_size) {
    sdf_march_kernel<<<2 * NBLK, THREADS>>>(
        (const float*)d_in[0],
        (const float*)d_in[1], (const float*)d_in[2],
        (const float*)d_in[3], (const float*)d_in[4],
        (const float*)d_in[5], (const float*)d_in[6],
        (const float*)d_in[7], (const float*)d_in[8],
        (const float*)d_in[9], (const float*)d_in[10],
        (float*)d_out);
}

// round 14
// speedup vs baseline: 1.5963x; 1.5963x over previous
#include <cuda_runtime.h>

typedef unsigned long long u64;
typedef unsigned int u32;

#define NRAYS 32768
#define THREADS 128
#define NCTA 296                 // 2 CTAs per SM on 148 SMs
#define N_MARCH_ITEMS 512        // 64 rays each (warp, 2 rays/thread)
#define N_SCAN_ITEMS  2048       // 512 ray-groups x 4 t-chunks
#define NITEMS (N_MARCH_ITEMS + N_SCAN_ITEMS)

__device__ u32 g_ticket;
__device__ u32 g_min[NRAYS];     // order-preserving-encoded partial mins

// ---- packed f32x2 helpers (Blackwell sm_103a) ----
__device__ __forceinline__ u64 pack2(float a, float b) {
    u64 r; asm("mov.b64 %0, {%1, %2};" : "=l"(r) : "f"(a), "f"(b)); return r;
}
__device__ __forceinline__ float2 unpack2(u64 v) {
    float2 r; asm("mov.b64 {%0, %1}, %2;" : "=f"(r.x), "=f"(r.y) : "l"(v)); return r;
}
__device__ __forceinline__ u64 ffma2(u64 a, u64 b, u64 c) {
    u64 d; asm("fma.rn.f32x2 %0, %1, %2, %3;" : "=l"(d) : "l"(a), "l"(b), "l"(c)); return d;
}
__device__ __forceinline__ u64 fadd2(u64 a, u64 b) {
    u64 d; asm("add.rn.f32x2 %0, %1, %2;" : "=l"(d) : "l"(a), "l"(b)); return d;
}
__device__ __forceinline__ u64 relu2(u64 v) {
    float2 f = unpack2(v);
    return pack2(fmaxf(f.x, 0.0f), fmaxf(f.y, 0.0f));
}
__device__ __forceinline__ u64 splat2(float x) { return pack2(x, x); }

// order-preserving float<->uint keys: enc(a) < enc(b) iff a < b (finite floats)
__device__ __forceinline__ u32 enc_f(float f) {
    u32 u = __float_as_uint(f);
    return (u & 0x80000000u) ? ~u : (u | 0x80000000u);
}
__device__ __forceinline__ float dec_f(u32 k) {
    return (k & 0x80000000u) ? __uint_as_float(k & 0x7FFFFFFFu)
                             : __uint_as_float(~k);
}

struct __align__(16) Weights {
    float W0[3 * 64];
    float b0[64];
    float W1[64 * 64];
    float b1[64];
    float W2[64];
    float b2;
    float pad[3];
    float Wr0[6 * 64];
    float br0[64];
    float Wr1[64 * 3];
    float br1[3];
};

// Two-point SDF eval — IDENTICAL to the verified R9 version (quarter-tile
// layer1, 207 regs, fma 61.8%). Every shared weight load feeds 4 ffma2
// (2 neurons x 2 rays). __noinline__ fences LICM of the weight loads.
__device__ __noinline__ float2 sdf_eval2(const Weights* __restrict__ sp,
                                         float pxA, float pyA, float pzA,
                                         float pxB, float pyB, float pzB) {
    const Weights& s = *sp;
    u64 hA[32], hB[32];
    {
        const float4* b4 = (const float4*)s.b0;
        #pragma unroll
        for (int q = 0; q < 16; q++) {
            float4 v = b4[q];
            u64 lo = pack2(v.x, v.y), hi = pack2(v.z, v.w);
            hA[2 * q] = lo; hA[2 * q + 1] = hi;
            hB[2 * q] = lo; hB[2 * q + 1] = hi;
        }
        float pa[3] = {pxA, pyA, pzA};
        float pb[3] = {pxB, pyB, pzB};
        #pragma unroll
        for (int i = 0; i < 3; i++) {
            u64 xA = splat2(pa[i]);
            u64 xB = splat2(pb[i]);
            const float4* w = (const float4*)(s.W0 + i * 64);
            #pragma unroll
            for (int q = 0; q < 16; q++) {
                float4 wv = w[q];
                u64 wlo = pack2(wv.x, wv.y), whi = pack2(wv.z, wv.w);
                hA[2 * q]     = ffma2(xA, wlo, hA[2 * q]);
                hA[2 * q + 1] = ffma2(xA, whi, hA[2 * q + 1]);
                hB[2 * q]     = ffma2(xB, wlo, hB[2 * q]);
                hB[2 * q + 1] = ffma2(xB, whi, hB[2 * q + 1]);
            }
        }
        #pragma unroll
        for (int q = 0; q < 32; q++) { hA[q] = relu2(hA[q]); hB[q] = relu2(hB[q]); }
    }

    u64 dA0 = 0ull, dA1 = 0ull, dB0 = 0ull, dB1 = 0ull;
    #pragma unroll 1
    for (int qt = 0; qt < 4; qt++) {
        u64 accA[8], accB[8];
        {
            const float4* b4 = (const float4*)(s.b1 + qt * 16);
            #pragma unroll
            for (int q = 0; q < 4; q++) {
                float4 v = b4[q];
                u64 lo = pack2(v.x, v.y), hi = pack2(v.z, v.w);
                accA[2 * q] = lo; accA[2 * q + 1] = hi;
                accB[2 * q] = lo; accB[2 * q + 1] = hi;
            }
        }
        const float4* wbase = (const float4*)(s.W1 + qt * 16);
        #pragma unroll
        for (int kk = 0; kk < 32; kk++) {
            float2 hpA = unpack2(hA[kk]);
            float2 hpB = unpack2(hB[kk]);
            {
                u64 xA = splat2(hpA.x), xB = splat2(hpB.x);
                const float4* w = wbase + (2 * kk) * 16;
                #pragma unroll
                for (int q = 0; q < 4; q++) {
                    float4 wv = w[q];
                    u64 wlo = pack2(wv.x, wv.y), whi = pack2(wv.z, wv.w);
                    accA[2 * q]     = ffma2(xA, wlo, accA[2 * q]);
                    accA[2 * q + 1] = ffma2(xA, whi, accA[2 * q + 1]);
                    accB[2 * q]     = ffma2(xB, wlo, accB[2 * q]);
                    accB[2 * q + 1] = ffma2(xB, whi, accB[2 * q + 1]);
                }
            }
            {
                u64 xA = splat2(hpA.y), xB = splat2(hpB.y);
                const float4* w = wbase + (2 * kk + 1) * 16;
                #pragma unroll
                for (int q = 0; q < 4; q++) {
                    float4 wv = w[q];
                    u64 wlo = pack2(wv.x, wv.y), whi = pack2(wv.z, wv.w);
                    accA[2 * q]     = ffma2(xA, wlo, accA[2 * q]);
                    accA[2 * q + 1] = ffma2(xA, whi, accA[2 * q + 1]);
                    accB[2 * q]     = ffma2(xB, wlo, accB[2 * q]);
                    accB[2 * q + 1] = ffma2(xB, whi, accB[2 * q + 1]);
                }
            }
        }
        const float4* w2 = (const float4*)(s.W2 + qt * 16);
        #pragma unroll
        for (int q = 0; q < 4; q++) {
            float4 wv = w2[q];
            u64 wlo = pack2(wv.x, wv.y), whi = pack2(wv.z, wv.w);
            dA0 = ffma2(relu2(accA[2 * q]),     wlo, dA0);
            dA1 = ffma2(relu2(accA[2 * q + 1]), whi, dA1);
            dB0 = ffma2(relu2(accB[2 * q]),     wlo, dB0);
            dB1 = ffma2(relu2(accB[2 * q + 1]), whi, dB1);
        }
    }
    float2 fa = unpack2(fadd2(dA0, dA1));
    float2 fb = unpack2(fadd2(dB0, dB1));
    return make_float2(fa.x + fa.y + s.b2, fb.x + fb.y + s.b2);
}

// Reflectance MLP (identical to R9).
__device__ __noinline__ void refl_eval(const Weights* __restrict__ sp,
                                       const float* in6, float* rgb) {
    const Weights& s = *sp;
    u64 h[32];
    {
        const float4* b4 = (const float4*)s.br0;
        #pragma unroll
        for (int q = 0; q < 16; q++) {
            float4 v = b4[q];
            h[2 * q]     = pack2(v.x, v.y);
            h[2 * q + 1] = pack2(v.z, v.w);
        }
        #pragma unroll
        for (int i = 0; i < 6; i++) {
            u64 xi = splat2(in6[i]);
            const float4* w = (const float4*)(s.Wr0 + i * 64);
            #pragma unroll
            for (int q = 0; q < 16; q++) {
                float4 wv = w[q];
                h[2 * q]     = ffma2(xi, pack2(wv.x, wv.y), h[2 * q]);
                h[2 * q + 1] = ffma2(xi, pack2(wv.z, wv.w), h[2 * q + 1]);
            }
        }
    }
    float a0 = s.br1[0], a1 = s.br1[1], a2 = s.br1[2];
    #pragma unroll
    for (int kk = 0; kk < 32; kk++) {
        float2 hp = unpack2(h[kk]);
        float v0 = fmaxf(hp.x, 0.0f);
        float v1 = fmaxf(hp.y, 0.0f);
        const float* w = s.Wr1 + (2 * kk) * 3;
        a0 = fmaf(v0, w[0], a0);
        a1 = fmaf(v0, w[1], a1);
        a2 = fmaf(v0, w[2], a2);
        a0 = fmaf(v1, w[3], a0);
        a1 = fmaf(v1, w[4], a1);
        a2 = fmaf(v1, w[5], a2);
    }
    rgb[0] = 1.0f / (1.0f + expf(-a0));
    rgb[1] = 1.0f / (1.0f + expf(-a1));
    rgb[2] = 1.0f / (1.0f + expf(-a2));
}

// Reset ticket + encoded-min scratch each replay (graph-deterministic).
__global__ void init_kernel() {
    int i = blockIdx.x * blockDim.x + threadIdx.x;
    if (i == 0) g_ticket = 0;
    if (i < NRAYS) g_min[i] = 0xFFFFFFFFu;   // +inf key
}

// Decode scan result into out[4r+3].
__global__ void finalize_kernel(float* __restrict__ out) {
    int r = blockIdx.x * blockDim.x + threadIdx.x;
    if (r < NRAYS) out[4 * r + 3] = dec_f(g_min[r]);
}

// Persistent kernel: 296 CTAs (2/SM), weights loaded once per CTA, then each
// WARP pulls items off a global ticket. Items in LPT order:
//   [0, 512):        march items  — ray group g=t, 64 rays, <=64 serial evals
//   [512, 2560):     scan chunks  — group g=(t-512)>>2, chunk c=(t-512)&3,
//                    t-indices c0:0..16, c1:17..32, c2:33..48, c3:49..64;
//                    partial min combined via encoded atomicMin (exact).
__global__ void __launch_bounds__(THREADS) sdf_persistent_kernel(
    const float* __restrict__ rays,
    const float* __restrict__ gW0, const float* __restrict__ gb0,
    const float* __restrict__ gW1, const float* __restrict__ gb1,
    const float* __restrict__ gW2, const float* __restrict__ gb2,
    const float* __restrict__ gWr0, const float* __restrict__ gbr0,
    const float* __restrict__ gWr1, const float* __restrict__ gbr1,
    float* __restrict__ out)
{
    __shared__ Weights s;
    int tid = threadIdx.x;
    for (int i = tid; i < 3 * 64; i += THREADS) s.W0[i] = gW0[i];
    for (int i = tid; i < 64; i += THREADS) s.b0[i] = gb0[i];
    for (int i = tid; i < 64 * 64; i += THREADS) s.W1[i] = gW1[i];
    for (int i = tid; i < 64; i += THREADS) s.b1[i] = gb1[i];
    for (int i = tid; i < 64; i += THREADS) s.W2[i] = gW2[i];
    if (tid == 0) s.b2 = gb2[0];
    for (int i = tid; i < 6 * 64; i += THREADS) s.Wr0[i] = gWr0[i];
    for (int i = tid; i < 64; i += THREADS) s.br0[i] = gbr0[i];
    for (int i = tid; i < 64 * 3; i += THREADS) s.Wr1[i] = gWr1[i];
    for (int i = tid; i < 3; i += THREADS) s.br1[i] = gbr1[i];
    __syncthreads();

    int lane = tid & 31;
    const float step = (1.0f + 1.0f / 64.0f) / 64.0f;  // 65/4096, exact fp32

    for (;;) {
        u32 item;
        if (lane == 0) item = atomicAdd(&g_ticket, 1u);
        item = __shfl_sync(0xffffffffu, item, 0);
        if (item >= NITEMS) break;

        if (item < N_MARCH_ITEMS) {
            // ---------------- march item: ray group = item ----------------
            int rayA = item * 64 + lane * 2;
            int rayB = rayA + 1;
            const float* ra = rays + rayA * 6;
            const float* rb = rays + rayB * 6;
            float roxA = ra[0], royA = ra[1], rozA = ra[2];
            float rdxA = ra[3], rdyA = ra[4], rdzA = ra[5];
            float roxB = rb[0], royB = rb[1], rozB = rb[2];
            float rdxB = rb[3], rdyB = rb[4], rdzB = rb[5];

            float cdA = 0.0f, cdB = 0.0f;
            bool hitA = false, hitB = false;
            #pragma unroll 1
            for (int it = 0; it < 64; ++it) {
                asm volatile("" ::: "memory");
                float2 d = sdf_eval2(&s,
                    fmaf(rdxA, cdA, roxA), fmaf(rdyA, cdA, royA), fmaf(rdzA, cdA, rozA),
                    fmaf(rdxB, cdB, roxB), fmaf(rdyB, cdB, royB), fmaf(rdzB, cdB, rozB));
                bool hA = (d.x < 1e-4f) && (cdA >= 0.0f) && (cdA <= 1.0f);
                bool hB = (d.y < 1e-4f) && (cdB >= 0.0f) && (cdB <= 1.0f);
                hitA = hitA || hA;
                hitB = hitB || hB;
                if (!hitA) cdA += d.x;
                if (!hitB) cdB += d.y;
                if (__all_sync(0xffffffffu, hitA && hitB)) break;
            }

            float rgbA[3] = {0.0f, 0.0f, 0.0f};
            float rgbB[3] = {0.0f, 0.0f, 0.0f};
            if (__any_sync(0xffffffffu, hitA || hitB)) {
                float in6A[6] = { fmaf(rdxA, cdA, roxA), fmaf(rdyA, cdA, royA),
                                  fmaf(rdzA, cdA, rozA), rdxA, rdyA, rdzA };
                refl_eval(&s, in6A, rgbA);
                float in6B[6] = { fmaf(rdxB, cdB, roxB), fmaf(rdyB, cdB, royB),
                                  fmaf(rdzB, cdB, rozB), rdxB, rdyB, rdzB };
                refl_eval(&s, in6B, rgbB);
                if (!hitA) { rgbA[0] = 0.0f; rgbA[1] = 0.0f; rgbA[2] = 0.0f; }
                if (!hitB) { rgbB[0] = 0.0f; rgbB[1] = 0.0f; rgbB[2] = 0.0f; }
            }
            out[4 * rayA + 0] = rgbA[0];
            out[4 * rayA + 1] = rgbA[1];
            out[4 * rayA + 2] = rgbA[2];
            out[4 * rayB + 0] = rgbB[0];
            out[4 * rayB + 1] = rgbB[1];
            out[4 * rayB + 2] = rgbB[2];
        } else {
            // ---------------- scan chunk ----------------
            u32 sc = item - N_MARCH_ITEMS;
            int g = (int)(sc >> 2);
            int c = (int)(sc & 3);
            int i0 = (c == 0) ? 0 : (16 * c + 1);
            int i1 = 16 * (c + 1);          // inclusive

            int rayA = g * 64 + lane * 2;
            int rayB = rayA + 1;
            const float* ra = rays + rayA * 6;
            const float* rb = rays + rayB * 6;
            float roxA = ra[0], royA = ra[1], rozA = ra[2];
            float rdxA = ra[3], rdyA = ra[4], rdzA = ra[5];
            float roxB = rb[0], royB = rb[1], rozB = rb[2];
            float rdxB = rb[3], rdyB = rb[4], rdzB = rb[5];

            float cmA = __int_as_float(0x7F800000);  // +inf
            float cmB = __int_as_float(0x7F800000);
            #pragma unroll 1
            for (int i = i0; i <= i1; ++i) {
                asm volatile("" ::: "memory");
                float t = step * (float)i;
                float2 sd = sdf_eval2(&s,
                    fmaf(rdxA, t, roxA), fmaf(rdyA, t, royA), fmaf(rdzA, t, rozA),
                    fmaf(rdxB, t, roxB), fmaf(rdyB, t, royB), fmaf(rdzB, t, rozB));
                cmA = fminf(cmA, sd.x);
                cmB = fminf(cmB, sd.y);
            }
            atomicMin(&g_min[rayA], enc_f(cmA));
            atomicMin(&g_min[rayB], enc_f(cmB));
        }
    }
}

extern "C" void kernel_launch(void* const* d_in, const int* in_sizes, int n_in,
                              void* d_out, int out_size) {
    init_kernel<<<(NRAYS + 255) / 256, 256>>>();
    sdf_persistent_kernel<<<NCTA, THREADS>>>(
        (const float*)d_in[0],
        (const float*)d_in[1], (const float*)d_in[2],
        (const float*)d_in[3], (const float*)d_in[4],
        (const float*)d_in[5], (const float*)d_in[6],
        (const float*)d_in[7], (const float*)d_in[8],
        (const float*)d_in[9], (const float*)d_in[10],
        (float*)d_out);
    finalize_kernel<<<(NRAYS + 255) / 256, 256>>>((float*)d_out);
}

// round 17
// speedup vs baseline: 1.8474x; 1.1573x over previous
#include <cuda_runtime.h>

typedef unsigned long long u64;

#define NRAYS 32768
#define THREADS 224              // 7 warps per CTA
#define NCTA 147                 // 1 CTA per SM (207 regs x 448 thr > 64K regs)
#define N_WORK_WARPS 1024        // 512 march + 512 scan warp-items

// ---- packed f32x2 helpers (Blackwell sm_103a) ----
__device__ __forceinline__ u64 pack2(float a, float b) {
    u64 r; asm("mov.b64 %0, {%1, %2};" : "=l"(r) : "f"(a), "f"(b)); return r;
}
__device__ __forceinline__ float2 unpack2(u64 v) {
    float2 r; asm("mov.b64 {%0, %1}, %2;" : "=f"(r.x), "=f"(r.y) : "l"(v)); return r;
}
__device__ __forceinline__ u64 ffma2(u64 a, u64 b, u64 c) {
    u64 d; asm("fma.rn.f32x2 %0, %1, %2, %3;" : "=l"(d) : "l"(a), "l"(b), "l"(c)); return d;
}
__device__ __forceinline__ u64 fadd2(u64 a, u64 b) {
    u64 d; asm("add.rn.f32x2 %0, %1, %2;" : "=l"(d) : "l"(a), "l"(b)); return d;
}
__device__ __forceinline__ u64 relu2(u64 v) {
    float2 f = unpack2(v);
    return pack2(fmaxf(f.x, 0.0f), fmaxf(f.y, 0.0f));
}
__device__ __forceinline__ u64 splat2(float x) { return pack2(x, x); }

struct __align__(16) Weights {
    float W0[3 * 64];
    float b0[64];
    float W1[64 * 64];
    float b1[64];
    float W2[64];
    float b2;
    float pad[3];
    float Wr0[6 * 64];
    float br0[64];
    float Wr1[64 * 3];
    float br1[3];
};

// Two-point SDF eval — IDENTICAL to the verified R9 version (quarter-tile
// layer1, 8 independent acc chains, ~207 regs, fma 61.8%). Every shared
// weight load feeds 4 ffma2 (2 neurons x 2 rays). __noinline__ fences LICM
// of the weight loads out of the march/scan loops (else ~10KB/thread spill).
__device__ __noinline__ float2 sdf_eval2(const Weights* __restrict__ sp,
                                         float pxA, float pyA, float pzA,
                                         float pxB, float pyB, float pzB) {
    const Weights& s = *sp;
    u64 hA[32], hB[32];
    {
        const float4* b4 = (const float4*)s.b0;
        #pragma unroll
        for (int q = 0; q < 16; q++) {
            float4 v = b4[q];
            u64 lo = pack2(v.x, v.y), hi = pack2(v.z, v.w);
            hA[2 * q] = lo; hA[2 * q + 1] = hi;
            hB[2 * q] = lo; hB[2 * q + 1] = hi;
        }
        float pa[3] = {pxA, pyA, pzA};
        float pb[3] = {pxB, pyB, pzB};
        #pragma unroll
        for (int i = 0; i < 3; i++) {
            u64 xA = splat2(pa[i]);
            u64 xB = splat2(pb[i]);
            const float4* w = (const float4*)(s.W0 + i * 64);
            #pragma unroll
            for (int q = 0; q < 16; q++) {
                float4 wv = w[q];
                u64 wlo = pack2(wv.x, wv.y), whi = pack2(wv.z, wv.w);
                hA[2 * q]     = ffma2(xA, wlo, hA[2 * q]);
                hA[2 * q + 1] = ffma2(xA, whi, hA[2 * q + 1]);
                hB[2 * q]     = ffma2(xB, wlo, hB[2 * q]);
                hB[2 * q + 1] = ffma2(xB, whi, hB[2 * q + 1]);
            }
        }
        #pragma unroll
        for (int q = 0; q < 32; q++) { hA[q] = relu2(hA[q]); hB[q] = relu2(hB[q]); }
    }

    u64 dA0 = 0ull, dA1 = 0ull, dB0 = 0ull, dB1 = 0ull;
    #pragma unroll 1
    for (int qt = 0; qt < 4; qt++) {
        u64 accA[8], accB[8];
        {
            const float4* b4 = (const float4*)(s.b1 + qt * 16);
            #pragma unroll
            for (int q = 0; q < 4; q++) {
                float4 v = b4[q];
                u64 lo = pack2(v.x, v.y), hi = pack2(v.z, v.w);
                accA[2 * q] = lo; accA[2 * q + 1] = hi;
                accB[2 * q] = lo; accB[2 * q + 1] = hi;
            }
        }
        const float4* wbase = (const float4*)(s.W1 + qt * 16);
        #pragma unroll
        for (int kk = 0; kk < 32; kk++) {
            float2 hpA = unpack2(hA[kk]);
            float2 hpB = unpack2(hB[kk]);
            {
                u64 xA = splat2(hpA.x), xB = splat2(hpB.x);
                const float4* w = wbase + (2 * kk) * 16;
                #pragma unroll
                for (int q = 0; q < 4; q++) {
                    float4 wv = w[q];
                    u64 wlo = pack2(wv.x, wv.y), whi = pack2(wv.z, wv.w);
                    accA[2 * q]     = ffma2(xA, wlo, accA[2 * q]);
                    accA[2 * q + 1] = ffma2(xA, whi, accA[2 * q + 1]);
                    accB[2 * q]     = ffma2(xB, wlo, accB[2 * q]);
                    accB[2 * q + 1] = ffma2(xB, whi, accB[2 * q + 1]);
                }
            }
            {
                u64 xA = splat2(hpA.y), xB = splat2(hpB.y);
                const float4* w = wbase + (2 * kk + 1) * 16;
                #pragma unroll
                for (int q = 0; q < 4; q++) {
                    float4 wv = w[q];
                    u64 wlo = pack2(wv.x, wv.y), whi = pack2(wv.z, wv.w);
                    accA[2 * q]     = ffma2(xA, wlo, accA[2 * q]);
                    accA[2 * q + 1] = ffma2(xA, whi, accA[2 * q + 1]);
                    accB[2 * q]     = ffma2(xB, wlo, accB[2 * q]);
                    accB[2 * q + 1] = ffma2(xB, whi, accB[2 * q + 1]);
                }
            }
        }
        const float4* w2 = (const float4*)(s.W2 + qt * 16);
        #pragma unroll
        for (int q = 0; q < 4; q++) {
            float4 wv = w2[q];
            u64 wlo = pack2(wv.x, wv.y), whi = pack2(wv.z, wv.w);
            dA0 = ffma2(relu2(accA[2 * q]),     wlo, dA0);
            dA1 = ffma2(relu2(accA[2 * q + 1]), whi, dA1);
            dB0 = ffma2(relu2(accB[2 * q]),     wlo, dB0);
            dB1 = ffma2(relu2(accB[2 * q + 1]), whi, dB1);
        }
    }
    float2 fa = unpack2(fadd2(dA0, dA1));
    float2 fb = unpack2(fadd2(dB0, dB1));
    return make_float2(fa.x + fa.y + s.b2, fb.x + fb.y + s.b2);
}

// Reflectance MLP (identical to R9).
__device__ __noinline__ void refl_eval(const Weights* __restrict__ sp,
                                       const float* in6, float* rgb) {
    const Weights& s = *sp;
    u64 h[32];
    {
        const float4* b4 = (const float4*)s.br0;
        #pragma unroll
        for (int q = 0; q < 16; q++) {
            float4 v = b4[q];
            h[2 * q]     = pack2(v.x, v.y);
            h[2 * q + 1] = pack2(v.z, v.w);
        }
        #pragma unroll
        for (int i = 0; i < 6; i++) {
            u64 xi = splat2(in6[i]);
            const float4* w = (const float4*)(s.Wr0 + i * 64);
            #pragma unroll
            for (int q = 0; q < 16; q++) {
                float4 wv = w[q];
                h[2 * q]     = ffma2(xi, pack2(wv.x, wv.y), h[2 * q]);
                h[2 * q + 1] = ffma2(xi, pack2(wv.z, wv.w), h[2 * q + 1]);
            }
        }
    }
    float a0 = s.br1[0], a1 = s.br1[1], a2 = s.br1[2];
    #pragma unroll
    for (int kk = 0; kk < 32; kk++) {
        float2 hp = unpack2(h[kk]);
        float v0 = fmaxf(hp.x, 0.0f);
        float v1 = fmaxf(hp.y, 0.0f);
        const float* w = s.Wr1 + (2 * kk) * 3;
        a0 = fmaf(v0, w[0], a0);
        a1 = fmaf(v0, w[1], a1);
        a2 = fmaf(v0, w[2], a2);
        a0 = fmaf(v1, w[3], a0);
        a1 = fmaf(v1, w[4], a1);
        a2 = fmaf(v1, w[5], a2);
    }
    rgb[0] = 1.0f / (1.0f + expf(-a0));
    rgb[1] = 1.0f / (1.0f + expf(-a1));
    rgb[2] = 1.0f / (1.0f + expf(-a2));
}

// 147 CTAs x 224 threads = 7 warps/CTA, hardware-pinned 1 CTA/SM (regs).
// Warp w = bid*7+wid takes work-item w: [0,512) march groups, [512,1024)
// scan groups; each group = 64 consecutive rays, 2 per thread. Uniform
// ~7 warps/SM removes the 8-vs-4 warp imbalance of the 256-CTA grid; every
// warp's workload is ~equal (march ~64 evals, scan 65). March early-exit
// frees issue slots for co-resident scan warps.
__global__ void __launch_bounds__(THREADS, 1) sdf_march_kernel(
    const float* __restrict__ rays,
    const float* __restrict__ gW0, const float* __restrict__ gb0,
    const float* __restrict__ gW1, const float* __restrict__ gb1,
    const float* __restrict__ gW2, const float* __restrict__ gb2,
    const float* __restrict__ gWr0, const float* __restrict__ gbr0,
    const float* __restrict__ gWr1, const float* __restrict__ gbr1,
    float* __restrict__ out)
{
    __shared__ Weights s;
    int tid = threadIdx.x;
    for (int i = tid; i < 3 * 64; i += THREADS) s.W0[i] = gW0[i];
    for (int i = tid; i < 64; i += THREADS) s.b0[i] = gb0[i];
    for (int i = tid; i < 64 * 64; i += THREADS) s.W1[i] = gW1[i];
    for (int i = tid; i < 64; i += THREADS) s.b1[i] = gb1[i];
    for (int i = tid; i < 64; i += THREADS) s.W2[i] = gW2[i];
    if (tid == 0) s.b2 = gb2[0];
    for (int i = tid; i < 6 * 64; i += THREADS) s.Wr0[i] = gWr0[i];
    for (int i = tid; i < 64; i += THREADS) s.br0[i] = gbr0[i];
    for (int i = tid; i < 64 * 3; i += THREADS) s.Wr1[i] = gWr1[i];
    for (int i = tid; i < 3; i += THREADS) s.br1[i] = gbr1[i];
    __syncthreads();

    int w = blockIdx.x * 7 + (tid >> 5);
    int lane = tid & 31;
    if (w >= N_WORK_WARPS) return;   // 5 surplus warps (after smem barrier)

    bool is_scan = w >= 512;
    int g = is_scan ? (w - 512) : w;
    int rayA = g * 64 + lane * 2;
    int rayB = rayA + 1;
    const float* ra = rays + rayA * 6;
    const float* rb = rays + rayB * 6;
    float roxA = ra[0], royA = ra[1], rozA = ra[2];
    float rdxA = ra[3], rdyA = ra[4], rdzA = ra[5];
    float roxB = rb[0], royB = rb[1], rozB = rb[2];
    float rdxB = rb[3], rdyB = rb[4], rdzB = rb[5];

    if (!is_scan) {
        // ---- sphere march (hit lanes freeze cd -> all-hit break is exact) ----
        float cdA = 0.0f, cdB = 0.0f;
        bool hitA = false, hitB = false;
        #pragma unroll 1
        for (int it = 0; it < 64; ++it) {
            asm volatile("" ::: "memory");   // block cross-iteration hoist/CSE
            float2 d = sdf_eval2(&s,
                fmaf(rdxA, cdA, roxA), fmaf(rdyA, cdA, royA), fmaf(rdzA, cdA, rozA),
                fmaf(rdxB, cdB, roxB), fmaf(rdyB, cdB, royB), fmaf(rdzB, cdB, rozB));
            bool hA = (d.x < 1e-4f) && (cdA >= 0.0f) && (cdA <= 1.0f);
            bool hB = (d.y < 1e-4f) && (cdB >= 0.0f) && (cdB <= 1.0f);
            hitA = hitA || hA;
            hitB = hitB || hB;
            if (!hitA) cdA += d.x;
            if (!hitB) cdB += d.y;
            if (__all_sync(0xffffffffu, hitA && hitB)) break;
        }

        // ---- reflectance (skipped entirely for all-miss warps) ----
        float rgbA[3] = {0.0f, 0.0f, 0.0f};
        float rgbB[3] = {0.0f, 0.0f, 0.0f};
        if (__any_sync(0xffffffffu, hitA || hitB)) {
            float in6A[6] = { fmaf(rdxA, cdA, roxA), fmaf(rdyA, cdA, royA),
                              fmaf(rdzA, cdA, rozA), rdxA, rdyA, rdzA };
            refl_eval(&s, in6A, rgbA);
            float in6B[6] = { fmaf(rdxB, cdB, roxB), fmaf(rdyB, cdB, royB),
                              fmaf(rdzB, cdB, rozB), rdxB, rdyB, rdzB };
            refl_eval(&s, in6B, rgbB);
            if (!hitA) { rgbA[0] = 0.0f; rgbA[1] = 0.0f; rgbA[2] = 0.0f; }
            if (!hitB) { rgbB[0] = 0.0f; rgbB[1] = 0.0f; rgbB[2] = 0.0f; }
        }
        out[4 * rayA + 0] = rgbA[0];
        out[4 * rayA + 1] = rgbA[1];
        out[4 * rayA + 2] = rgbA[2];
        out[4 * rayB + 0] = rgbB[0];
        out[4 * rayB + 1] = rgbB[1];
        out[4 * rayB + 2] = rgbB[2];
    } else {
        // ---- throughput argmin scan: t = step*i, i = 0..64 ----
        // tput = sdf(best_pos) equals the scan's running min (same weight
        // values, identical position arithmetic), so only the min is tracked.
        const float step = (1.0f + 1.0f / 64.0f) / 64.0f;  // 65/4096, exact fp32
        float2 cm = sdf_eval2(&s, roxA, royA, rozA, roxB, royB, rozB);
        #pragma unroll 1
        for (int i = 1; i <= 64; ++i) {
            asm volatile("" ::: "memory");   // block cross-iteration hoist/CSE
            float t = step * (float)i;
            float2 sd = sdf_eval2(&s,
                fmaf(rdxA, t, roxA), fmaf(rdyA, t, royA), fmaf(rdzA, t, rozA),
                fmaf(rdxB, t, roxB), fmaf(rdyB, t, royB), fmaf(rdzB, t, rozB));
            cm.x = fminf(cm.x, sd.x);
            cm.y = fminf(cm.y, sd.y);
        }
        out[4 * rayA + 3] = cm.x;
        out[4 * rayB + 3] = cm.y;
    }
}

extern "C" void kernel_launch(void* const* d_in, const int* in_sizes, int n_in,
                              void* d_out, int out_size) {
    sdf_march_kernel<<<NCTA, THREADS>>>(
        (const float*)d_in[0],
        (const float*)d_in[1], (const float*)d_in[2],
        (const float*)d_in[3], (const float*)d_in[4],
        (const float*)d_in[5], (const float*)d_in[6],
        (const float*)d_in[7], (const float*)d_in[8],
        (const float*)d_in[9], (const float*)d_in[10],
        (float*)d_out);
}